// round 11
// baseline (speedup 1.0000x reference)
#include <cuda_runtime.h>
#include <math.h>

#define BATCH 4096
#define D     64
#define HDIM  256
#define G3    768
#define KC    208
#define KPAD  224
#define NK    20

// ---------------- scratch (device globals: no allocation allowed) ----------------
__device__ float g_gi[(size_t)BATCH * G3];          // 12.6 MB : cbm @ W_ih[:,1:]^T + b_ih
__device__ float g_c1[(size_t)BATCH * HDIM];        //  4.2 MB : cbm @ W1[:,256:]^T + b1
__device__ float g_hs[(size_t)BATCH * D * HDIM];    //  268 MB : GRU hidden states
__device__ float g_ll[(size_t)BATCH * D];           //    1 MB : per-position log-likelihood

// ---------------------------------------------------------------------------
// Shared micro-kernel: acc[4][8] += As[32 x 256] * B[256(g) x 256(k)]^T-ish
// B element layout: Bmat[g*ldb + k].  rows r = w + 8j, cols c = lane + 32i.
// Wt staged in smem with stride 257 (conflict-free).
// ---------------------------------------------------------------------------
__device__ __forceinline__ void mm_chunk256(
    float acc[4][8],
    const float* __restrict__ Bmat, int ldb,
    const float* As,           // smem, stride 256
    float* Wt, int tid)
{
    const int lane = tid & 31;
    const int w    = tid >> 5;
#pragma unroll 1
    for (int kt = 0; kt < 8; ++kt) {
        const int k0 = kt * 32;
#pragma unroll
        for (int it = 0; it < 32; ++it) {
            int g = it * 8 + w;                         // 0..255, unique per (it,w)
            Wt[lane * 257 + g] = Bmat[g * ldb + k0 + lane];  // coalesced LDG, conflict-free STS
        }
        __syncthreads();
#pragma unroll
        for (int kk = 0; kk < 32; ++kk) {
            float a0 = As[(w +  0) * 256 + k0 + kk];    // warp-broadcast
            float a1 = As[(w +  8) * 256 + k0 + kk];
            float a2 = As[(w + 16) * 256 + k0 + kk];
            float a3 = As[(w + 24) * 256 + k0 + kk];
            const float* wrow = &Wt[kk * 257 + lane];
#pragma unroll
            for (int i = 0; i < 8; ++i) {
                float wv = wrow[32 * i];                // conflict-free LDS
                acc[0][i] = fmaf(a0, wv, acc[0][i]);
                acc[1][i] = fmaf(a1, wv, acc[1][i]);
                acc[2][i] = fmaf(a2, wv, acc[2][i]);
                acc[3][i] = fmaf(a3, wv, acc[3][i]);
            }
        }
        __syncthreads();
    }
}

// ---------------------------------------------------------------------------
// Kernel 1: out = cbm @ Bmat[:, colOff:colOff+208]^T + bias   (K = 208, padded 224)
// which==0 -> g_gi (ldout 768, grid.y=3), which==1 -> g_c1 (ldout 256, grid.y=1)
// ---------------------------------------------------------------------------
__global__ void __launch_bounds__(256) gemm_cbm_kernel(
    const float* __restrict__ c, const float* __restrict__ bb, const float* __restrict__ mmat,
    const float* __restrict__ Bmat, int ldb, int colOff,
    const float* __restrict__ bias, int which, int ldout)
{
    extern __shared__ float sm[];
    float* As = sm;                 // 32*224
    float* Wt = As + 32 * KPAD;     // 32*257
    float* outp = which ? g_c1 : g_gi;

    const int tid  = threadIdx.x;
    const int lane = tid & 31, w = tid >> 5;
    const int row0 = blockIdx.x * 32;
    const int gb   = blockIdx.y * 256;

    for (int idx = tid; idx < 32 * KPAD; idx += 256) {
        int r = idx / KPAD, j = idx - r * KPAD;
        int br = row0 + r;
        float v = 0.f;
        if (j < 80)        v = c[br * 80 + j];
        else if (j < 144)  v = bb[br * 64 + (j - 80)];
        else if (j < KC)   v = mmat[br * 64 + (j - 144)];
        As[idx] = v;
    }
    __syncthreads();

    float acc[4][8];
#pragma unroll
    for (int j = 0; j < 4; ++j)
#pragma unroll
        for (int i = 0; i < 8; ++i) acc[j][i] = 0.f;

#pragma unroll 1
    for (int kt = 0; kt < 7; ++kt) {
        const int k0 = kt * 32;
        const int kcol = k0 + lane;
#pragma unroll
        for (int it = 0; it < 32; ++it) {
            int g = it * 8 + w;
            float v = 0.f;
            if (kcol < KC) v = Bmat[(gb + g) * ldb + colOff + kcol];
            Wt[lane * 257 + g] = v;
        }
        __syncthreads();
#pragma unroll
        for (int kk = 0; kk < 32; ++kk) {
            float a0 = As[(w +  0) * KPAD + k0 + kk];
            float a1 = As[(w +  8) * KPAD + k0 + kk];
            float a2 = As[(w + 16) * KPAD + k0 + kk];
            float a3 = As[(w + 24) * KPAD + k0 + kk];
            const float* wrow = &Wt[kk * 257 + lane];
#pragma unroll
            for (int i = 0; i < 8; ++i) {
                float wv = wrow[32 * i];
                acc[0][i] = fmaf(a0, wv, acc[0][i]);
                acc[1][i] = fmaf(a1, wv, acc[1][i]);
                acc[2][i] = fmaf(a2, wv, acc[2][i]);
                acc[3][i] = fmaf(a3, wv, acc[3][i]);
            }
        }
        __syncthreads();
    }
#pragma unroll
    for (int j = 0; j < 4; ++j) {
        int r = row0 + w + 8 * j;
#pragma unroll
        for (int i = 0; i < 8; ++i) {
            int cc = gb + lane + 32 * i;
            outp[(size_t)r * ldout + cc] = acc[j][i] + bias[cc];
        }
    }
}

// ---------------------------------------------------------------------------
// Kernel 2: persistent batch-split GRU. 128 CTAs x 32 rows, 64 steps.
// gi (incl b_ih) lives in smem; W_hh streamed from L2 each chunk.
// ---------------------------------------------------------------------------
__global__ void __launch_bounds__(256) gru_kernel(
    const float* __restrict__ z, const float* __restrict__ Wih,
    const float* __restrict__ Whh, const float* __restrict__ bhh_g)
{
    extern __shared__ float sm[];
    float* hS   = sm;                   // 32*256
    float* giS  = hS  + 32 * 256;       // 32*768
    float* Wt   = giS + 32 * 768;       // 32*257
    float* zr   = Wt  + 32 * 257;       // 32*64
    float* wzS  = zr  + 32 * 64;        // 768  (W_ih[:,0])
    float* bhhS = wzS + 768;            // 768

    const int tid  = threadIdx.x;
    const int lane = tid & 31, w = tid >> 5;
    const int row0 = blockIdx.x * 32;

    for (int i = tid; i < 32 * 256; i += 256) hS[i] = 0.f;
    for (int i = tid; i < 32 * 768; i += 256) giS[i] = g_gi[(size_t)row0 * G3 + i];
    for (int i = tid; i < 32 * 64;  i += 256) zr[i]  = z[(size_t)row0 * D + i];
    for (int i = tid; i < 768; i += 256) { wzS[i] = Wih[i * 209]; bhhS[i] = bhh_g[i]; }
    __syncthreads();

    float Rn[4][8];   // r-gate, then n-gate (same thread owns same (row,col) in all chunks)

    for (int t = 0; t < D; ++t) {
        float zp[4];
#pragma unroll
        for (int j = 0; j < 4; ++j)
            zp[j] = (t == 0) ? -1.f : zr[(w + 8 * j) * 64 + (t - 1)];

        float acc[4][8];
        // ---- chunk r (gate rows 0..255) ----
#pragma unroll
        for (int j = 0; j < 4; ++j)
#pragma unroll
            for (int i = 0; i < 8; ++i) acc[j][i] = 0.f;
        mm_chunk256(acc, Whh, 256, hS, Wt, tid);
#pragma unroll
        for (int j = 0; j < 4; ++j) {
            int r = w + 8 * j;
#pragma unroll
            for (int i = 0; i < 8; ++i) {
                int g = lane + 32 * i;
                float gate = giS[r * 768 + g] + zp[j] * wzS[g] + acc[j][i] + bhhS[g];
                Rn[j][i] = 1.f / (1.f + expf(-gate));
            }
        }
        // ---- chunk n (gate rows 512..767), uses r in registers ----
#pragma unroll
        for (int j = 0; j < 4; ++j)
#pragma unroll
            for (int i = 0; i < 8; ++i) acc[j][i] = 0.f;
        mm_chunk256(acc, Whh + 512 * 256, 256, hS, Wt, tid);
#pragma unroll
        for (int j = 0; j < 4; ++j) {
            int r = w + 8 * j;
#pragma unroll
            for (int i = 0; i < 8; ++i) {
                int g = 512 + lane + 32 * i;
                float ghn = acc[j][i] + bhhS[g];
                float nin = giS[r * 768 + g] + zp[j] * wzS[g] + Rn[j][i] * ghn;
                Rn[j][i] = tanhf(nin);
            }
        }
        // ---- chunk u (gate rows 256..511), then h update ----
#pragma unroll
        for (int j = 0; j < 4; ++j)
#pragma unroll
            for (int i = 0; i < 8; ++i) acc[j][i] = 0.f;
        mm_chunk256(acc, Whh + 256 * 256, 256, hS, Wt, tid);
#pragma unroll
        for (int j = 0; j < 4; ++j) {
            int r = w + 8 * j;
#pragma unroll
            for (int i = 0; i < 8; ++i) {
                int cidx = lane + 32 * i;
                int g = 256 + cidx;
                float u = 1.f / (1.f + expf(-(giS[r * 768 + g] + zp[j] * wzS[g]
                                              + acc[j][i] + bhhS[g])));
                int hidx = r * 256 + cidx;
                float hn = (1.f - u) * Rn[j][i] + u * hS[hidx];
                hS[hidx] = hn;
                g_hs[((size_t)(row0 + r) * D + t) * HDIM + cidx] = hn;
            }
        }
        __syncthreads();
    }
}

// ---------------------------------------------------------------------------
// Kernel 3: fused MLP + mixture log-likelihood. 8192 CTAs, 32 positions each.
// ---------------------------------------------------------------------------
__global__ void __launch_bounds__(256, 2) mlp_kernel(
    const float* __restrict__ z,
    const float* __restrict__ W1, const float* __restrict__ W2, const float* __restrict__ W3,
    const float* __restrict__ b2, const float* __restrict__ b3)
{
    extern __shared__ float sm[];
    float* A   = sm;              // 32*256  (hs, later a2)
    float* O   = A   + 8192;      // 32*256  (a1)
    float* Wt  = O   + 8192;      // 32*257
    float* prm = Wt  + 8224;      // 32*65
    float* c1s = prm + 2080;      // 256
    float* b2s = c1s + 256;       // 256
    float* b3s = b2s + 256;       // 64
    float* zs  = b3s + 64;        // 32

    const int tid  = threadIdx.x;
    const int lane = tid & 31, w = tid >> 5;
    const int bId  = blockIdx.x >> 1;
    const int t0   = (blockIdx.x & 1) * 32;
    const size_t hbase = ((size_t)bId * D + t0) * HDIM;

    for (int i = tid; i < 8192; i += 256) A[i] = g_hs[hbase + i];
    if (tid < 256) { c1s[tid] = g_c1[(size_t)bId * HDIM + tid]; b2s[tid] = b2[tid]; }
    if (tid < 64)  b3s[tid] = (tid < 60) ? b3[tid] : 0.f;
    if (tid < 32)  zs[tid] = z[(size_t)bId * D + t0 + tid];
    __syncthreads();

    float acc[4][8];
    // ---- layer 1: A @ W1[:, :256]^T, +c1 (already has b1 + cbm part), tanh ----
#pragma unroll
    for (int j = 0; j < 4; ++j)
#pragma unroll
        for (int i = 0; i < 8; ++i) acc[j][i] = 0.f;
    mm_chunk256(acc, W1, 464, A, Wt, tid);
#pragma unroll
    for (int j = 0; j < 4; ++j) {
        int r = w + 8 * j;
#pragma unroll
        for (int i = 0; i < 8; ++i) {
            int cc = lane + 32 * i;
            O[r * 256 + cc] = tanhf(acc[j][i] + c1s[cc]);
        }
    }
    // ---- layer 2: O @ W2^T + b2, tanh -> A ----
#pragma unroll
    for (int j = 0; j < 4; ++j)
#pragma unroll
        for (int i = 0; i < 8; ++i) acc[j][i] = 0.f;
    mm_chunk256(acc, W2, 256, O, Wt, tid);
#pragma unroll
    for (int j = 0; j < 4; ++j) {
        int r = w + 8 * j;
#pragma unroll
        for (int i = 0; i < 8; ++i) {
            int cc = lane + 32 * i;
            A[r * 256 + cc] = tanhf(acc[j][i] + b2s[cc]);
        }
    }
    // ---- layer 3: A @ W3^T + b3, N=60 (padded 64) ----
    float acc3[4][2];
#pragma unroll
    for (int j = 0; j < 4; ++j) { acc3[j][0] = 0.f; acc3[j][1] = 0.f; }
#pragma unroll 1
    for (int kt = 0; kt < 8; ++kt) {
        const int k0 = kt * 32;
#pragma unroll
        for (int it = 0; it < 8; ++it) {
            int g = it * 8 + w;                                   // 0..63
            Wt[lane * 65 + g] = (g < 60) ? W3[g * 256 + k0 + lane] : 0.f;
        }
        __syncthreads();
#pragma unroll
        for (int kk = 0; kk < 32; ++kk) {
            float a0 = A[(w +  0) * 256 + k0 + kk];
            float a1 = A[(w +  8) * 256 + k0 + kk];
            float a2 = A[(w + 16) * 256 + k0 + kk];
            float a3 = A[(w + 24) * 256 + k0 + kk];
            const float* wrow = &Wt[kk * 65 + lane];
#pragma unroll
            for (int i = 0; i < 2; ++i) {
                float wv = wrow[32 * i];
                acc3[0][i] = fmaf(a0, wv, acc3[0][i]);
                acc3[1][i] = fmaf(a1, wv, acc3[1][i]);
                acc3[2][i] = fmaf(a2, wv, acc3[2][i]);
                acc3[3][i] = fmaf(a3, wv, acc3[3][i]);
            }
        }
        __syncthreads();
    }
#pragma unroll
    for (int j = 0; j < 4; ++j) {
        int r = w + 8 * j;
#pragma unroll
        for (int i = 0; i < 2; ++i) {
            int cc = lane + 32 * i;
            if (cc < 60) prm[r * 65 + cc] = acc3[j][i] + b3s[cc];
        }
    }
    __syncthreads();

    // ---- mixture log-likelihood epilogue (1 thread per row) ----
    if (tid < 32) {
        const int row = tid;
        const float zt = zs[row];
        const float HALF_L2PI = 0.91893853320467274178f;   // 0.5*log(2*pi)
        float av[NK];
        float m1 = -1e30f, m2 = -1e30f;
#pragma unroll
        for (int k = 0; k < NK; ++k) {
            float lg = prm[row * 65 + k];
            float mu = prm[row * 65 + 20 + k];
            float ls = prm[row * 65 + 40 + k];
            float dd = (zt - mu) * expf(-ls);
            float a  = lg - ls - HALF_L2PI - 0.5f * dd * dd;
            av[k] = a;
            m1 = fmaxf(m1, a);
            m2 = fmaxf(m2, lg);
        }
        float s1 = 0.f, s2 = 0.f;
#pragma unroll
        for (int k = 0; k < NK; ++k) {
            s1 += expf(av[k] - m1);
            s2 += expf(prm[row * 65 + k] - m2);
        }
        g_ll[(size_t)bId * D + t0 + row] = (m1 + logf(s1)) - (m2 + logf(s2));
    }
}

// ---------------------------------------------------------------------------
// Kernel 4: masked sum. sort of a 0/1 vector = prefix of ones -> popc + prefix.
// One warp per batch row.
// ---------------------------------------------------------------------------
__global__ void reduce_kernel(const float* __restrict__ bmat,
                              const float* __restrict__ mmat,
                              float* __restrict__ out)
{
    int gwarp = (blockIdx.x * blockDim.x + threadIdx.x) >> 5;
    int lane  = threadIdx.x & 31;
    if (gwarp >= BATCH) return;
    const float* br = bmat + (size_t)gwarp * D;
    const float* mr = mmat + (size_t)gwarp * D;
    bool q0 = (mr[lane]      > 0.5f) && (br[lane]      < 0.5f);
    bool q1 = (mr[lane + 32] > 0.5f) && (br[lane + 32] < 0.5f);
    int count = __popc(__ballot_sync(0xffffffffu, q0))
              + __popc(__ballot_sync(0xffffffffu, q1));
    float s = 0.f;
    const float* ll = g_ll + (size_t)gwarp * D;
    if (lane      < count) s += ll[lane];
    if (lane + 32 < count) s += ll[lane + 32];
#pragma unroll
    for (int off = 16; off > 0; off >>= 1)
        s += __shfl_xor_sync(0xffffffffu, s, off);
    if (lane == 0) out[gwarp] = s;
}

// ---------------------------------------------------------------------------
extern "C" void kernel_launch(void* const* d_in, const int* in_sizes, int n_in,
                              void* d_out, int out_size)
{
    (void)in_sizes; (void)n_in; (void)out_size;
    const float* z    = (const float*)d_in[0];
    const float* c    = (const float*)d_in[1];
    const float* b_   = (const float*)d_in[2];
    const float* m_   = (const float*)d_in[3];
    const float* W_ih = (const float*)d_in[4];
    const float* W_hh = (const float*)d_in[5];
    const float* b_ih = (const float*)d_in[6];
    const float* b_hh = (const float*)d_in[7];
    const float* W1   = (const float*)d_in[8];
    const float* b1   = (const float*)d_in[9];
    const float* W2   = (const float*)d_in[10];
    const float* b2   = (const float*)d_in[11];
    const float* W3   = (const float*)d_in[12];
    const float* b3   = (const float*)d_in[13];
    float* out = (float*)d_out;

    const size_t smem_cbm = (32 * KPAD + 32 * 257) * sizeof(float);                    //  ~60 KB
    const size_t smem_gru = (32*256 + 32*768 + 32*257 + 32*64 + 768 + 768) * sizeof(float); // ~174 KB
    const size_t smem_mlp = (8192 + 8192 + 8224 + 2080 + 256 + 256 + 64 + 32) * sizeof(float); // ~107 KB

    cudaFuncSetAttribute((const void*)gemm_cbm_kernel,
                         cudaFuncAttributeMaxDynamicSharedMemorySize, (int)smem_cbm);
    cudaFuncSetAttribute((const void*)gru_kernel,
                         cudaFuncAttributeMaxDynamicSharedMemorySize, (int)smem_gru);
    cudaFuncSetAttribute((const void*)mlp_kernel,
                         cudaFuncAttributeMaxDynamicSharedMemorySize, (int)smem_mlp);

    // gi = cbm @ W_ih[:,1:209]^T + b_ih        [4096 x 768]
    gemm_cbm_kernel<<<dim3(128, 3), 256, smem_cbm>>>(c, b_, m_, W_ih, 209, 1, b_ih, 0, G3);
    // c1 = cbm @ W1[:,256:464]^T + b1          [4096 x 256]
    gemm_cbm_kernel<<<dim3(128, 1), 256, smem_cbm>>>(c, b_, m_, W1, 464, 256, b1, 1, HDIM);
    // GRU: 64 steps, batch-split persistent CTAs
    gru_kernel<<<128, 256, smem_gru>>>(z, W_ih, W_hh, b_hh);
    // MLP + loglik per (b, t)
    mlp_kernel<<<BATCH * 2, 256, smem_mlp>>>(z, W1, W2, W3, b2, b3);
    // masked sum (sort of 0/1 mask == prefix count)
    reduce_kernel<<<(BATCH * 32) / 256, 256>>>(b_, m_, out);
}

// round 13
// speedup vs baseline: 1.1582x; 1.1582x over previous
#include <cuda_runtime.h>
#include <math.h>
#include <stdint.h>

#define BATCH 4096
#define D     64
#define HDIM  256
#define G3    768
#define KC    208
#define KPAD  224
#define NK    20
#define WTS   258          // Wt stride (even -> 8B-aligned pairs, 2-way STS conflict only)

typedef unsigned long long u64;

// ---------------- scratch (device globals: no allocation allowed) ----------------
__device__ float g_gi[(size_t)BATCH * G3];          // cbm @ W_ih[:,1:]^T + b_ih
__device__ float g_c1[(size_t)BATCH * HDIM];        // cbm @ W1[:,256:]^T + b1
__device__ float g_hs[(size_t)BATCH * D * HDIM];    // GRU hidden states
__device__ float g_ll[(size_t)BATCH * D];           // per-position log-likelihood

// ======================= packed f32x2 helpers =======================
__device__ __forceinline__ u64 pack2(float x, float y) {
    u64 r; asm("mov.b64 %0, {%1,%2};" : "=l"(r) : "f"(x), "f"(y)); return r;
}
__device__ __forceinline__ float2 unpack2(u64 v) {
    float2 f; asm("mov.b64 {%0,%1}, %2;" : "=f"(f.x), "=f"(f.y) : "l"(v)); return f;
}
__device__ __forceinline__ void ffma2(u64& d, u64 a, u64 b) {
    asm("fma.rn.f32x2 %0, %1, %2, %0;" : "+l"(d) : "l"(a), "l"(b));
}

// ---------------------------------------------------------------------------
// Packed micro-kernel: acc[4][4] (each a f32x2 pair) += As[32x256] * B^T.
// B layout: Bmat[g*ldb + k]. Thread owns rows w+8j, column pairs 2*lane+64*i.
// ---------------------------------------------------------------------------
__device__ __forceinline__ void mm2_chunk256(
    u64 acc[4][4], const float* __restrict__ Bmat, int ldb,
    const float* As, float* Wt, int tid)
{
    const int lane = tid & 31;
    const int w    = tid >> 5;
#pragma unroll 1
    for (int kt = 0; kt < 8; ++kt) {
        const int k0 = kt * 32;
#pragma unroll
        for (int it = 0; it < 32; ++it) {
            int g = it * 8 + w;                       // 0..255 unique per (it,w)
            Wt[lane * WTS + g] = Bmat[g * ldb + k0 + lane];   // coalesced LDG
        }
        __syncthreads();
#pragma unroll
        for (int kk = 0; kk < 32; ++kk) {
            float s0 = As[(w +  0) * 256 + k0 + kk];  // warp-broadcast LDS
            float s1 = As[(w +  8) * 256 + k0 + kk];
            float s2 = As[(w + 16) * 256 + k0 + kk];
            float s3 = As[(w + 24) * 256 + k0 + kk];
            u64 a0 = pack2(s0, s0), a1 = pack2(s1, s1);
            u64 a2 = pack2(s2, s2), a3 = pack2(s3, s3);
            const float* wbase = Wt + kk * WTS + 2 * lane;
#pragma unroll
            for (int i = 0; i < 4; ++i) {
                u64 wp = *(const u64*)(wbase + 64 * i);   // LDS.64, conflict-free
                ffma2(acc[0][i], a0, wp);
                ffma2(acc[1][i], a1, wp);
                ffma2(acc[2][i], a2, wp);
                ffma2(acc[3][i], a3, wp);
            }
        }
        __syncthreads();
    }
}

// ---------------------------------------------------------------------------
// Kernel 1: out = cbm @ Bmat[:, colOff:colOff+208]^T + bias   (K=208 pad 224)
// ---------------------------------------------------------------------------
__global__ void __launch_bounds__(256) gemm_cbm_kernel(
    const float* __restrict__ c, const float* __restrict__ bb, const float* __restrict__ mmat,
    const float* __restrict__ Bmat, int ldb, int colOff,
    const float* __restrict__ bias, int which, int ldout)
{
    extern __shared__ float sm[];
    float* As = sm;                 // 32*224
    float* Wt = As + 32 * KPAD;     // 32*258
    float* outp = which ? g_c1 : g_gi;

    const int tid  = threadIdx.x;
    const int lane = tid & 31, w = tid >> 5;
    const int row0 = blockIdx.x * 32;
    const int gb   = blockIdx.y * 256;

    for (int idx = tid; idx < 32 * KPAD; idx += 256) {
        int r = idx / KPAD, j = idx - r * KPAD;
        int br = row0 + r;
        float v = 0.f;
        if (j < 80)        v = c[br * 80 + j];
        else if (j < 144)  v = bb[br * 64 + (j - 80)];
        else if (j < KC)   v = mmat[br * 64 + (j - 144)];
        As[idx] = v;
    }
    __syncthreads();

    u64 acc[4][4];
#pragma unroll
    for (int j = 0; j < 4; ++j)
#pragma unroll
        for (int i = 0; i < 4; ++i) acc[j][i] = 0ull;

#pragma unroll 1
    for (int kt = 0; kt < 7; ++kt) {
        const int k0 = kt * 32;
        const int kcol = k0 + lane;
#pragma unroll
        for (int it = 0; it < 32; ++it) {
            int g = it * 8 + w;
            float v = 0.f;
            if (kcol < KC) v = Bmat[(gb + g) * ldb + colOff + kcol];
            Wt[lane * WTS + g] = v;
        }
        __syncthreads();
#pragma unroll
        for (int kk = 0; kk < 32; ++kk) {
            float s0 = As[(w +  0) * KPAD + k0 + kk];
            float s1 = As[(w +  8) * KPAD + k0 + kk];
            float s2 = As[(w + 16) * KPAD + k0 + kk];
            float s3 = As[(w + 24) * KPAD + k0 + kk];
            u64 a0 = pack2(s0, s0), a1 = pack2(s1, s1);
            u64 a2 = pack2(s2, s2), a3 = pack2(s3, s3);
            const float* wbase = Wt + kk * WTS + 2 * lane;
#pragma unroll
            for (int i = 0; i < 4; ++i) {
                u64 wp = *(const u64*)(wbase + 64 * i);
                ffma2(acc[0][i], a0, wp);
                ffma2(acc[1][i], a1, wp);
                ffma2(acc[2][i], a2, wp);
                ffma2(acc[3][i], a3, wp);
            }
        }
        __syncthreads();
    }
#pragma unroll
    for (int j = 0; j < 4; ++j) {
        int r = row0 + w + 8 * j;
#pragma unroll
        for (int i = 0; i < 4; ++i) {
            int cc = gb + 2 * lane + 64 * i;
            float2 av = unpack2(acc[j][i]);
            float2 bi = *(const float2*)(bias + cc);
            float2 ov; ov.x = av.x + bi.x; ov.y = av.y + bi.y;
            *(float2*)(outp + (size_t)r * ldout + cc) = ov;
        }
    }
}

// ---------------------------------------------------------------------------
// Kernel 2: persistent batch-split GRU. 128 CTAs x 32 rows, 64 steps.
// ---------------------------------------------------------------------------
__global__ void __launch_bounds__(256) gru_kernel(
    const float* __restrict__ z, const float* __restrict__ Wih,
    const float* __restrict__ Whh, const float* __restrict__ bhh_g)
{
    extern __shared__ float sm[];
    float* hS   = sm;                   // 32*256
    float* giS  = hS  + 32 * 256;       // 32*768
    float* Wt   = giS + 32 * 768;       // 32*258
    float* zr   = Wt  + 32 * WTS;       // 32*64
    float* wzS  = zr  + 32 * 64;        // 768
    float* bhhS = wzS + 768;            // 768

    const int tid  = threadIdx.x;
    const int lane = tid & 31, w = tid >> 5;
    const int row0 = blockIdx.x * 32;

    for (int i = tid; i < 32 * 256; i += 256) hS[i] = 0.f;
    for (int i = tid; i < 32 * 768; i += 256) giS[i] = g_gi[(size_t)row0 * G3 + i];
    for (int i = tid; i < 32 * 64;  i += 256) zr[i]  = z[(size_t)row0 * D + i];
    for (int i = tid; i < 768; i += 256) { wzS[i] = Wih[i * 209]; bhhS[i] = bhh_g[i]; }
    __syncthreads();

    float Rn[4][8];   // r-gate then n-gate, mapping (j, 2i / 2i+1)

    for (int t = 0; t < D; ++t) {
        float zp[4];
#pragma unroll
        for (int j = 0; j < 4; ++j)
            zp[j] = (t == 0) ? -1.f : zr[(w + 8 * j) * 64 + (t - 1)];

        u64 acc[4][4];
        // ---- chunk r (gate rows 0..255) ----
#pragma unroll
        for (int j = 0; j < 4; ++j)
#pragma unroll
            for (int i = 0; i < 4; ++i) acc[j][i] = 0ull;
        mm2_chunk256(acc, Whh, 256, hS, Wt, tid);
#pragma unroll
        for (int j = 0; j < 4; ++j) {
            int r = w + 8 * j;
#pragma unroll
            for (int i = 0; i < 4; ++i) {
                int g = 2 * lane + 64 * i;
                float2 av = unpack2(acc[j][i]);
                float2 gi2 = *(const float2*)(giS + r * 768 + g);
                float2 wz2 = *(const float2*)(wzS + g);
                float2 bh2 = *(const float2*)(bhhS + g);
                float gx = gi2.x + zp[j] * wz2.x + av.x + bh2.x;
                float gy = gi2.y + zp[j] * wz2.y + av.y + bh2.y;
                Rn[j][2 * i]     = 1.f / (1.f + expf(-gx));
                Rn[j][2 * i + 1] = 1.f / (1.f + expf(-gy));
            }
        }
        // ---- chunk n (gate rows 512..767), r in registers ----
#pragma unroll
        for (int j = 0; j < 4; ++j)
#pragma unroll
            for (int i = 0; i < 4; ++i) acc[j][i] = 0ull;
        mm2_chunk256(acc, Whh + 512 * 256, 256, hS, Wt, tid);
#pragma unroll
        for (int j = 0; j < 4; ++j) {
            int r = w + 8 * j;
#pragma unroll
            for (int i = 0; i < 4; ++i) {
                int g = 512 + 2 * lane + 64 * i;
                float2 av = unpack2(acc[j][i]);
                float2 gi2 = *(const float2*)(giS + r * 768 + g);
                float2 wz2 = *(const float2*)(wzS + g);
                float2 bh2 = *(const float2*)(bhhS + g);
                float nx = gi2.x + zp[j] * wz2.x + Rn[j][2 * i]     * (av.x + bh2.x);
                float ny = gi2.y + zp[j] * wz2.y + Rn[j][2 * i + 1] * (av.y + bh2.y);
                Rn[j][2 * i]     = tanhf(nx);
                Rn[j][2 * i + 1] = tanhf(ny);
            }
        }
        // ---- chunk u (gate rows 256..511), then h update ----
#pragma unroll
        for (int j = 0; j < 4; ++j)
#pragma unroll
            for (int i = 0; i < 4; ++i) acc[j][i] = 0ull;
        mm2_chunk256(acc, Whh + 256 * 256, 256, hS, Wt, tid);
#pragma unroll
        for (int j = 0; j < 4; ++j) {
            int r = w + 8 * j;
#pragma unroll
            for (int i = 0; i < 4; ++i) {
                int cidx = 2 * lane + 64 * i;
                int g = 256 + cidx;
                float2 av = unpack2(acc[j][i]);
                float2 gi2 = *(const float2*)(giS + r * 768 + g);
                float2 wz2 = *(const float2*)(wzS + g);
                float2 bh2 = *(const float2*)(bhhS + g);
                float ux = 1.f / (1.f + expf(-(gi2.x + zp[j] * wz2.x + av.x + bh2.x)));
                float uy = 1.f / (1.f + expf(-(gi2.y + zp[j] * wz2.y + av.y + bh2.y)));
                float2 hold = *(const float2*)(hS + r * 256 + cidx);
                float2 hn;
                hn.x = (1.f - ux) * Rn[j][2 * i]     + ux * hold.x;
                hn.y = (1.f - uy) * Rn[j][2 * i + 1] + uy * hold.y;
                *(float2*)(hS + r * 256 + cidx) = hn;
                *(float2*)(g_hs + ((size_t)(row0 + r) * D + t) * HDIM + cidx) = hn;
            }
        }
        __syncthreads();
    }
}

// ---------------------------------------------------------------------------
// Kernel 3: fused MLP + mixture log-likelihood. 8192 CTAs, 32 positions each.
// ---------------------------------------------------------------------------
__global__ void __launch_bounds__(256, 2) mlp_kernel(
    const float* __restrict__ z,
    const float* __restrict__ W1, const float* __restrict__ W2, const float* __restrict__ W3,
    const float* __restrict__ b2, const float* __restrict__ b3)
{
    extern __shared__ float sm[];
    float* A   = sm;              // 32*256  (hs, later a2)
    float* O   = A   + 8192;      // 32*256  (a1)
    float* Wt  = O   + 8192;      // 32*258
    float* prm = Wt  + 32 * WTS;  // 32*66
    float* c1s = prm + 32 * 66;   // 256
    float* b2s = c1s + 256;       // 256
    float* b3s = b2s + 256;       // 64
    float* zs  = b3s + 64;        // 32

    const int tid  = threadIdx.x;
    const int lane = tid & 31, w = tid >> 5;
    const int bId  = blockIdx.x >> 1;
    const int t0   = (blockIdx.x & 1) * 32;
    const size_t hbase = ((size_t)bId * D + t0) * HDIM;

    for (int i = tid; i < 8192; i += 256) A[i] = g_hs[hbase + i];
    if (tid < 256) { c1s[tid] = g_c1[(size_t)bId * HDIM + tid]; b2s[tid] = b2[tid]; }
    if (tid < 64)  b3s[tid] = (tid < 60) ? b3[tid] : 0.f;
    if (tid < 32)  zs[tid] = z[(size_t)bId * D + t0 + tid];
    __syncthreads();

    u64 acc[4][4];
    // ---- layer 1: A @ W1[:, :256]^T, +c1 (has b1 + cbm part), tanh ----
#pragma unroll
    for (int j = 0; j < 4; ++j)
#pragma unroll
        for (int i = 0; i < 4; ++i) acc[j][i] = 0ull;
    mm2_chunk256(acc, W1, 464, A, Wt, tid);
#pragma unroll
    for (int j = 0; j < 4; ++j) {
        int r = w + 8 * j;
#pragma unroll
        for (int i = 0; i < 4; ++i) {
            int cc = 2 * lane + 64 * i;
            float2 av = unpack2(acc[j][i]);
            float2 ci = *(const float2*)(c1s + cc);
            float2 ov; ov.x = tanhf(av.x + ci.x); ov.y = tanhf(av.y + ci.y);
            *(float2*)(O + r * 256 + cc) = ov;
        }
    }
    // ---- layer 2: O @ W2^T + b2, tanh -> A ----
#pragma unroll
    for (int j = 0; j < 4; ++j)
#pragma unroll
        for (int i = 0; i < 4; ++i) acc[j][i] = 0ull;
    mm2_chunk256(acc, W2, 256, O, Wt, tid);
#pragma unroll
    for (int j = 0; j < 4; ++j) {
        int r = w + 8 * j;
#pragma unroll
        for (int i = 0; i < 4; ++i) {
            int cc = 2 * lane + 64 * i;
            float2 av = unpack2(acc[j][i]);
            float2 bi = *(const float2*)(b2s + cc);
            float2 ov; ov.x = tanhf(av.x + bi.x); ov.y = tanhf(av.y + bi.y);
            *(float2*)(A + r * 256 + cc) = ov;
        }
    }
    // ---- layer 3: A @ W3^T + b3, N=60 (padded 64) ----
    u64 acc3[4];
#pragma unroll
    for (int j = 0; j < 4; ++j) acc3[j] = 0ull;
#pragma unroll 1
    for (int kt = 0; kt < 8; ++kt) {
        const int k0 = kt * 32;
#pragma unroll
        for (int it = 0; it < 8; ++it) {
            int g = it * 8 + w;                                   // 0..63
            Wt[lane * 66 + g] = (g < 60) ? W3[g * 256 + k0 + lane] : 0.f;
        }
        __syncthreads();
#pragma unroll
        for (int kk = 0; kk < 32; ++kk) {
            float s0 = A[(w +  0) * 256 + k0 + kk];
            float s1 = A[(w +  8) * 256 + k0 + kk];
            float s2 = A[(w + 16) * 256 + k0 + kk];
            float s3 = A[(w + 24) * 256 + k0 + kk];
            u64 a0 = pack2(s0, s0), a1 = pack2(s1, s1);
            u64 a2 = pack2(s2, s2), a3 = pack2(s3, s3);
            u64 wp = *(const u64*)(Wt + kk * 66 + 2 * lane);
            ffma2(acc3[0], a0, wp);
            ffma2(acc3[1], a1, wp);
            ffma2(acc3[2], a2, wp);
            ffma2(acc3[3], a3, wp);
        }
        __syncthreads();
    }
#pragma unroll
    for (int j = 0; j < 4; ++j) {
        int r = w + 8 * j;
        int cc = 2 * lane;
        float2 av = unpack2(acc3[j]);
        float2 bi = *(const float2*)(b3s + cc);
        float2 ov; ov.x = av.x + bi.x; ov.y = av.y + bi.y;
        *(float2*)(prm + r * 66 + cc) = ov;
    }
    __syncthreads();

    // ---- mixture log-likelihood epilogue (1 thread per row) ----
    if (tid < 32) {
        const int row = tid;
        const float zt = zs[row];
        const float HALF_L2PI = 0.91893853320467274178f;   // 0.5*log(2*pi)
        float av[NK];
        float m1 = -1e30f, m2 = -1e30f;
#pragma unroll
        for (int k = 0; k < NK; ++k) {
            float lg = prm[row * 66 + k];
            float mu = prm[row * 66 + 20 + k];
            float ls = prm[row * 66 + 40 + k];
            float dd = (zt - mu) * expf(-ls);
            float a  = lg - ls - HALF_L2PI - 0.5f * dd * dd;
            av[k] = a;
            m1 = fmaxf(m1, a);
            m2 = fmaxf(m2, lg);
        }
        float s1 = 0.f, s2 = 0.f;
#pragma unroll
        for (int k = 0; k < NK; ++k) {
            s1 += expf(av[k] - m1);
            s2 += expf(prm[row * 66 + k] - m2);
        }
        g_ll[(size_t)bId * D + t0 + row] = (m1 + logf(s1)) - (m2 + logf(s2));
    }
}

// ---------------------------------------------------------------------------
// Kernel 4: masked sum (sort of 0/1 mask == prefix count). One warp per row.
// ---------------------------------------------------------------------------
__global__ void reduce_kernel(const float* __restrict__ bmat,
                              const float* __restrict__ mmat,
                              float* __restrict__ out)
{
    int gwarp = (blockIdx.x * blockDim.x + threadIdx.x) >> 5;
    int lane  = threadIdx.x & 31;
    if (gwarp >= BATCH) return;
    const float* br = bmat + (size_t)gwarp * D;
    const float* mr = mmat + (size_t)gwarp * D;
    bool q0 = (mr[lane]      > 0.5f) && (br[lane]      < 0.5f);
    bool q1 = (mr[lane + 32] > 0.5f) && (br[lane + 32] < 0.5f);
    int count = __popc(__ballot_sync(0xffffffffu, q0))
              + __popc(__ballot_sync(0xffffffffu, q1));
    float s = 0.f;
    const float* ll = g_ll + (size_t)gwarp * D;
    if (lane      < count) s += ll[lane];
    if (lane + 32 < count) s += ll[lane + 32];
#pragma unroll
    for (int off = 16; off > 0; off >>= 1)
        s += __shfl_xor_sync(0xffffffffu, s, off);
    if (lane == 0) out[gwarp] = s;
}

// ---------------------------------------------------------------------------
extern "C" void kernel_launch(void* const* d_in, const int* in_sizes, int n_in,
                              void* d_out, int out_size)
{
    (void)in_sizes; (void)n_in; (void)out_size;
    const float* z    = (const float*)d_in[0];
    const float* c    = (const float*)d_in[1];
    const float* b_   = (const float*)d_in[2];
    const float* m_   = (const float*)d_in[3];
    const float* W_ih = (const float*)d_in[4];
    const float* W_hh = (const float*)d_in[5];
    const float* b_ih = (const float*)d_in[6];
    const float* b_hh = (const float*)d_in[7];
    const float* W1   = (const float*)d_in[8];
    const float* b1   = (const float*)d_in[9];
    const float* W2   = (const float*)d_in[10];
    const float* b2   = (const float*)d_in[11];
    const float* W3   = (const float*)d_in[12];
    const float* b3   = (const float*)d_in[13];
    float* out = (float*)d_out;

    const size_t smem_cbm = (32 * KPAD + 32 * WTS) * sizeof(float);
    const size_t smem_gru = (32*256 + 32*768 + 32*WTS + 32*64 + 768 + 768) * sizeof(float);
    const size_t smem_mlp = (8192 + 8192 + 32*WTS + 32*66 + 256 + 256 + 64 + 32) * sizeof(float);

    cudaFuncSetAttribute((const void*)gemm_cbm_kernel,
                         cudaFuncAttributeMaxDynamicSharedMemorySize, (int)smem_cbm);
    cudaFuncSetAttribute((const void*)gru_kernel,
                         cudaFuncAttributeMaxDynamicSharedMemorySize, (int)smem_gru);
    cudaFuncSetAttribute((const void*)mlp_kernel,
                         cudaFuncAttributeMaxDynamicSharedMemorySize, (int)smem_mlp);

    gemm_cbm_kernel<<<dim3(128, 3), 256, smem_cbm>>>(c, b_, m_, W_ih, 209, 1, b_ih, 0, G3);
    gemm_cbm_kernel<<<dim3(128, 1), 256, smem_cbm>>>(c, b_, m_, W1, 464, 256, b1, 1, HDIM);
    gru_kernel<<<128, 256, smem_gru>>>(z, W_ih, W_hh, b_hh);
    mlp_kernel<<<BATCH * 2, 256, smem_mlp>>>(z, W1, W2, W3, b2, b3);
    reduce_kernel<<<(BATCH * 32) / 256, 256>>>(b_, m_, out);
}